// round 15
// baseline (speedup 1.0000x reference)
#include <cuda_runtime.h>
#include <cuda_bf16.h>
#include <stdint.h>
#include <math.h>

#define EMBED 512
#define HEADS 8
#define HD 64
#define BB 4
#define SS 2048
#define MROWS (BB * SS) /* 8192 */
#define NBH (BB * HEADS) /* 32 */

// ------------------------- scratch (no allocs allowed) ----------------------
__device__ float g_v[(size_t)MROWS * EMBED];
__device__ float g_attn[(size_t)NBH * SS * SS];
__device__ __nv_bfloat16 g_qh[(size_t)MROWS * EMBED];
__device__ __nv_bfloat16 g_ql[(size_t)MROWS * EMBED];
__device__ __nv_bfloat16 g_kh[(size_t)MROWS * EMBED];
__device__ __nv_bfloat16 g_kl[(size_t)MROWS * EMBED];
__device__ __nv_bfloat16 g_ctxh[(size_t)MROWS * EMBED];
__device__ __nv_bfloat16 g_ctxl[(size_t)MROWS * EMBED];
__device__ __nv_bfloat16 g_vth[(size_t)NBH * HD * SS];
__device__ __nv_bfloat16 g_vtl[(size_t)NBH * HD * SS];
__device__ __nv_bfloat16 g_wth[4 * EMBED * EMBED];
__device__ __nv_bfloat16 g_wtl[4 * EMBED * EMBED];

// ------------------------- helpers -----------------------------------------
__device__ __forceinline__ uint32_t smem_u32(const void* p) {
    uint32_t a;
    asm("{ .reg .u64 t; cvta.to.shared.u64 t, %1; cvt.u32.u64 %0, t; }" : "=r"(a) : "l"(p));
    return a;
}

#define LDSM_X4(r0, r1, r2, r3, a) \
    asm volatile("ldmatrix.sync.aligned.m8n8.x4.shared.b16 {%0,%1,%2,%3}, [%4];" \
                 : "=r"(r0), "=r"(r1), "=r"(r2), "=r"(r3) : "r"(a))

#define MMA_BF16(d, a0, a1, a2, a3, b0, b1) \
    asm volatile("mma.sync.aligned.m16n8k16.row.col.f32.bf16.bf16.f32 " \
                 "{%0,%1,%2,%3}, {%4,%5,%6,%7}, {%8,%9}, {%0,%1,%2,%3};" \
                 : "+f"((d)[0]), "+f"((d)[1]), "+f"((d)[2]), "+f"((d)[3]) \
                 : "r"(a0), "r"(a1), "r"(a2), "r"(a3), "r"(b0), "r"(b1))

__device__ __forceinline__ void split2(float a, float b, uint32_t& h, uint32_t& l) {
    __nv_bfloat16 ha = __float2bfloat16(a), hb = __float2bfloat16(b);
    float la = a - __bfloat162float(ha), lb = b - __bfloat162float(hb);
    __nv_bfloat16 lla = __float2bfloat16(la), llb = __float2bfloat16(lb);
    h = ((uint32_t)__bfloat16_as_ushort(hb) << 16) | (uint32_t)__bfloat16_as_ushort(ha);
    l = ((uint32_t)__bfloat16_as_ushort(llb) << 16) | (uint32_t)__bfloat16_as_ushort(lla);
}

#define TSTRB 144
#define TILE128B (128 * TSTRB) /* 18432 */
#define TILE64B  (64 * TSTRB)  /* 9216  */

// ---------------------------------------------------------------------------
// Weight transpose + split (all 4 weights, one launch)
// ---------------------------------------------------------------------------
__global__ __launch_bounds__(256) void split_wT_all(
    const float* __restrict__ W0, const float* __restrict__ W1,
    const float* __restrict__ W2, const float* __restrict__ W3,
    __nv_bfloat16* __restrict__ th, __nv_bfloat16* __restrict__ tl)
{
    __shared__ float tile[32][33];
    const int z = blockIdx.z;
    const float* W = (z == 0) ? W0 : (z == 1) ? W1 : (z == 2) ? W2 : W3;
    __nv_bfloat16* tho = th + (size_t)z * EMBED * EMBED;
    __nv_bfloat16* tlo = tl + (size_t)z * EMBED * EMBED;
    const int n0 = blockIdx.x * 32, k0 = blockIdx.y * 32;
    const int tx = threadIdx.x, ty = threadIdx.y;
    #pragma unroll
    for (int j = 0; j < 4; j++)
        tile[ty + j * 8][tx] = W[(size_t)(k0 + ty + j * 8) * EMBED + n0 + tx];
    __syncthreads();
    #pragma unroll
    for (int j = 0; j < 4; j++) {
        int nl = ty + j * 8;
        float f = tile[tx][nl];
        __nv_bfloat16 hb = __float2bfloat16(f);
        __nv_bfloat16 lb = __float2bfloat16(f - __bfloat162float(hb));
        size_t o = (size_t)(n0 + nl) * EMBED + k0 + tx;
        tho[o] = hb;
        tlo[o] = lb;
    }
}

// ---------------------------------------------------------------------------
// V transpose + split
// ---------------------------------------------------------------------------
__global__ __launch_bounds__(256) void split_vT_kernel(
    const float* __restrict__ v, __nv_bfloat16* __restrict__ vth, __nv_bfloat16* __restrict__ vtl)
{
    __shared__ float tile[32][33];
    const int bh = blockIdx.z, b = bh >> 3, h = bh & 7;
    const int s0 = blockIdx.x * 32, d0 = blockIdx.y * 32;
    const int tx = threadIdx.x, ty = threadIdx.y;
    #pragma unroll
    for (int j = 0; j < 4; j++) {
        int sl = ty + j * 8;
        tile[sl][tx] = v[(size_t)(b * SS + s0 + sl) * EMBED + h * HD + d0 + tx];
    }
    __syncthreads();
    #pragma unroll
    for (int j = 0; j < 4; j++) {
        int dl = ty + j * 8;
        float f = tile[tx][dl];
        __nv_bfloat16 hb = __float2bfloat16(f);
        __nv_bfloat16 lb = __float2bfloat16(f - __bfloat162float(hb));
        size_t o = ((size_t)bh * HD + d0 + dl) * SS + s0 + tx;
        vth[o] = hb;
        vtl[o] = lb;
    }
}

// ---------------------------------------------------------------------------
// Shared 128x64-tile mma loop (context_mma shape): warps 4x2, warp 32x32.
// A tiles at OA_H/OA_L (128 x TSTRB), B tiles at OB_H/OB_L (64 x TSTRB).
// ---------------------------------------------------------------------------
#define P64_SMEM (2 * TILE128B + 2 * TILE64B) /* 55296 */

__device__ __forceinline__ void mma_128x64_step(
    uint32_t sb, int wm, int wn, uint32_t a_r, uint32_t a_c,
    uint32_t b_r, uint32_t b_c, float acc[2][4][4])
{
    const uint32_t OA_H = 0, OA_L = TILE128B, OB_H = 2 * TILE128B, OB_L = 2 * TILE128B + TILE64B;
    #pragma unroll
    for (int ks = 0; ks < 4; ks++) {
        const uint32_t kb = ks * 32;
        uint32_t a[2][4], bhf[2][4], blf[2][4];
        #pragma unroll
        for (int mf = 0; mf < 2; mf++) {
            uint32_t ad = sb + OA_H + (wm * 32 + mf * 16 + a_r) * TSTRB + kb + a_c;
            LDSM_X4(a[mf][0], a[mf][1], a[mf][2], a[mf][3], ad);
        }
        #pragma unroll
        for (int p = 0; p < 2; p++) {
            uint32_t bd = sb + OB_H + (wn * 32 + p * 16 + b_r) * TSTRB + kb + b_c;
            LDSM_X4(bhf[p][0], bhf[p][1], bhf[p][2], bhf[p][3], bd);
        }
        #pragma unroll
        for (int p = 0; p < 2; p++) {
            uint32_t bd = sb + OB_L + (wn * 32 + p * 16 + b_r) * TSTRB + kb + b_c;
            LDSM_X4(blf[p][0], blf[p][1], blf[p][2], blf[p][3], bd);
        }
        #pragma unroll
        for (int mf = 0; mf < 2; mf++)
            #pragma unroll
            for (int nf = 0; nf < 4; nf++) {
                MMA_BF16(acc[mf][nf], a[mf][0], a[mf][1], a[mf][2], a[mf][3],
                         bhf[nf >> 1][(nf & 1) * 2], bhf[nf >> 1][(nf & 1) * 2 + 1]);
                MMA_BF16(acc[mf][nf], a[mf][0], a[mf][1], a[mf][2], a[mf][3],
                         blf[nf >> 1][(nf & 1) * 2], blf[nf >> 1][(nf & 1) * 2 + 1]);
            }
        #pragma unroll
        for (int mf = 0; mf < 2; mf++) {
            uint32_t ad = sb + OA_L + (wm * 32 + mf * 16 + a_r) * TSTRB + kb + a_c;
            LDSM_X4(a[mf][0], a[mf][1], a[mf][2], a[mf][3], ad);
        }
        #pragma unroll
        for (int mf = 0; mf < 2; mf++)
            #pragma unroll
            for (int nf = 0; nf < 4; nf++)
                MMA_BF16(acc[mf][nf], a[mf][0], a[mf][1], a[mf][2], a[mf][3],
                         bhf[nf >> 1][(nf & 1) * 2], bhf[nf >> 1][(nf & 1) * 2 + 1]);
    }
}

// ---------------------------------------------------------------------------
// QKV projection: 128x64 tile, A raw fp32 (inline split), W pre-split.
// mode 0: fp32 out (V).  mode 1: bf16 hi/lo out (Q, K).
// ---------------------------------------------------------------------------
__global__ __launch_bounds__(256) void proj_qkv64(
    const float* __restrict__ A,
    const __nv_bfloat16* __restrict__ wth, const __nv_bfloat16* __restrict__ wtl,
    const float* __restrict__ bias,
    float* __restrict__ cf, __nv_bfloat16* __restrict__ ch, __nv_bfloat16* __restrict__ cl,
    int mode)
{
    extern __shared__ char smem[];
    const uint32_t sb = smem_u32(smem);
    const int tid = threadIdx.x, wid = tid >> 5, lane = tid & 31;
    const int row0 = blockIdx.y * 128, col0 = blockIdx.x * 64;
    const uint32_t OA_H = 0, OA_L = TILE128B, OB_H = 2 * TILE128B, OB_L = 2 * TILE128B + TILE64B;

    const int wm = wid >> 1, wn = wid & 1;
    float acc[2][4][4] = {};

    const uint32_t a_r = lane & 15, a_c = (lane >> 4) * 16;
    const uint32_t b_r = (lane & 7) + ((lane >> 4) & 1) * 8;
    const uint32_t b_c = ((lane >> 3) & 1) * 16;
    const int arow = tid >> 1, ahalf = tid & 1;
    const int brow = tid >> 2, bq = tid & 3;

    for (int kc = 0; kc < EMBED; kc += 64) {
        __syncthreads();
        {
            const float4* ap = (const float4*)(A + (size_t)(row0 + arow) * EMBED + kc + ahalf * 32);
            const uint32_t so = (uint32_t)arow * TSTRB + ahalf * 64;
            #pragma unroll
            for (int i = 0; i < 8; i++) {
                float4 f = ap[i];
                uint32_t h0, l0, h1, l1;
                split2(f.x, f.y, h0, l0);
                split2(f.z, f.w, h1, l1);
                *(uint2*)(smem + OA_H + so + i * 8) = make_uint2(h0, h1);
                *(uint2*)(smem + OA_L + so + i * 8) = make_uint2(l0, l1);
            }
        }
        {
            size_t o = (size_t)(col0 + brow) * EMBED + kc + bq * 16;
            const uint4* sh = (const uint4*)(wth + o);
            const uint4* sl = (const uint4*)(wtl + o);
            const uint32_t so = (uint32_t)brow * TSTRB + bq * 32;
            #pragma unroll
            for (int i = 0; i < 2; i++) {
                *(uint4*)(smem + OB_H + so + i * 16) = sh[i];
                *(uint4*)(smem + OB_L + so + i * 16) = sl[i];
            }
        }
        __syncthreads();
        mma_128x64_step(sb, wm, wn, a_r, a_c, b_r, b_c, acc);
    }

    const int er = lane >> 2, ec = (lane & 3) * 2;
    #pragma unroll
    for (int mf = 0; mf < 2; mf++) {
        int r = row0 + wm * 32 + mf * 16 + er;
        #pragma unroll
        for (int nf = 0; nf < 4; nf++) {
            int c = col0 + wn * 32 + nf * 8 + ec;
            float b0 = bias[c], b1 = bias[c + 1];
            float v00 = acc[mf][nf][0] + b0, v01 = acc[mf][nf][1] + b1;
            float v10 = acc[mf][nf][2] + b0, v11 = acc[mf][nf][3] + b1;
            if (mode == 0) {
                *(float2*)&cf[(size_t)r * EMBED + c] = make_float2(v00, v01);
                *(float2*)&cf[(size_t)(r + 8) * EMBED + c] = make_float2(v10, v11);
            } else {
                uint32_t h0, l0, h1, l1;
                split2(v00, v01, h0, l0);
                split2(v10, v11, h1, l1);
                *(uint32_t*)&ch[(size_t)r * EMBED + c] = h0;
                *(uint32_t*)&cl[(size_t)r * EMBED + c] = l0;
                *(uint32_t*)&ch[(size_t)(r + 8) * EMBED + c] = h1;
                *(uint32_t*)&cl[(size_t)(r + 8) * EMBED + c] = l1;
            }
        }
    }
}

// ---------------------------------------------------------------------------
// Output projection: 128x64 tile, A = ctx bf16 hi/lo, fp32 out.
// ---------------------------------------------------------------------------
__global__ __launch_bounds__(256) void proj_out64(
    const __nv_bfloat16* __restrict__ ah, const __nv_bfloat16* __restrict__ al,
    const __nv_bfloat16* __restrict__ wth, const __nv_bfloat16* __restrict__ wtl,
    const float* __restrict__ bias, float* __restrict__ cf)
{
    extern __shared__ char smem[];
    const uint32_t sb = smem_u32(smem);
    const int tid = threadIdx.x, wid = tid >> 5, lane = tid & 31;
    const int row0 = blockIdx.y * 128, col0 = blockIdx.x * 64;
    const uint32_t OA_H = 0, OA_L = TILE128B, OB_H = 2 * TILE128B, OB_L = 2 * TILE128B + TILE64B;

    const int wm = wid >> 1, wn = wid & 1;
    float acc[2][4][4] = {};

    const uint32_t a_r = lane & 15, a_c = (lane >> 4) * 16;
    const uint32_t b_r = (lane & 7) + ((lane >> 4) & 1) * 8;
    const uint32_t b_c = ((lane >> 3) & 1) * 16;
    const int arow = tid >> 1, ahalf = tid & 1;
    const int brow = tid >> 2, bq = tid & 3;

    for (int kc = 0; kc < EMBED; kc += 64) {
        __syncthreads();
        {
            size_t ao = (size_t)(row0 + arow) * EMBED + kc + ahalf * 32;
            const uint4* hp = (const uint4*)(ah + ao);
            const uint4* lp = (const uint4*)(al + ao);
            const uint32_t so = (uint32_t)arow * TSTRB + ahalf * 64;
            #pragma unroll
            for (int i = 0; i < 4; i++) {
                *(uint4*)(smem + OA_H + so + i * 16) = hp[i];
                *(uint4*)(smem + OA_L + so + i * 16) = lp[i];
            }
        }
        {
            size_t o = (size_t)(col0 + brow) * EMBED + kc + bq * 16;
            const uint4* sh = (const uint4*)(wth + o);
            const uint4* sl = (const uint4*)(wtl + o);
            const uint32_t so = (uint32_t)brow * TSTRB + bq * 32;
            #pragma unroll
            for (int i = 0; i < 2; i++) {
                *(uint4*)(smem + OB_H + so + i * 16) = sh[i];
                *(uint4*)(smem + OB_L + so + i * 16) = sl[i];
            }
        }
        __syncthreads();
        mma_128x64_step(sb, wm, wn, a_r, a_c, b_r, b_c, acc);
    }

    const int er = lane >> 2, ec = (lane & 3) * 2;
    #pragma unroll
    for (int mf = 0; mf < 2; mf++) {
        int r = row0 + wm * 32 + mf * 16 + er;
        #pragma unroll
        for (int nf = 0; nf < 4; nf++) {
            int c = col0 + wn * 32 + nf * 8 + ec;
            float b0 = bias[c], b1 = bias[c + 1];
            *(float2*)&cf[(size_t)r * EMBED + c] =
                make_float2(acc[mf][nf][0] + b0, acc[mf][nf][1] + b1);
            *(float2*)&cf[(size_t)(r + 8) * EMBED + c] =
                make_float2(acc[mf][nf][2] + b0, acc[mf][nf][3] + b1);
        }
    }
}

// ---------------------------------------------------------------------------
// Scores via mma.sync [R4 verbatim]
// ---------------------------------------------------------------------------
#define SC_SMEM (4 * TILE128B) /* 73728 */
__global__ __launch_bounds__(256) void scores_mma(
    const __nv_bfloat16* __restrict__ qh, const __nv_bfloat16* __restrict__ ql,
    const __nv_bfloat16* __restrict__ kh, const __nv_bfloat16* __restrict__ kl,
    float* __restrict__ attn)
{
    extern __shared__ char smem[];
    const uint32_t sb = smem_u32(smem);
    const int tid = threadIdx.x, wid = tid >> 5, lane = tid & 31;
    const int bh = blockIdx.z, b = bh >> 3, h = bh & 7;
    const int row0 = blockIdx.y * 128, col0 = blockIdx.x * 128;
    const uint32_t OA_H = 0, OA_L = TILE128B, OB_H = 2 * TILE128B, OB_L = 3 * TILE128B;

    {
        const int lrow = tid >> 1, lhalf = tid & 1;
        size_t qo = (size_t)(b * SS + row0 + lrow) * EMBED + h * HD + lhalf * 32;
        size_t ko = (size_t)(b * SS + col0 + lrow) * EMBED + h * HD + lhalf * 32;
        const uint4* qhp = (const uint4*)(qh + qo);
        const uint4* qlp = (const uint4*)(ql + qo);
        const uint4* khp = (const uint4*)(kh + ko);
        const uint4* klp = (const uint4*)(kl + ko);
        const uint32_t so = (uint32_t)lrow * TSTRB + lhalf * 64;
        #pragma unroll
        for (int i = 0; i < 4; i++) {
            *(uint4*)(smem + OA_H + so + i * 16) = qhp[i];
            *(uint4*)(smem + OA_L + so + i * 16) = qlp[i];
            *(uint4*)(smem + OB_H + so + i * 16) = khp[i];
            *(uint4*)(smem + OB_L + so + i * 16) = klp[i];
        }
    }
    __syncthreads();

    const int wm = wid >> 2, wn = wid & 3;
    float acc[4][4][4] = {};
    const uint32_t a_r = lane & 15, a_c = (lane >> 4) * 16;
    const uint32_t b_r = (lane & 7) + ((lane >> 4) & 1) * 8;
    const uint32_t b_c = ((lane >> 3) & 1) * 16;

    #pragma unroll
    for (int ks = 0; ks < 4; ks++) {
        const uint32_t kb = ks * 32;
        uint32_t a[4][4], bhf[2][4], blf[2][4];
        #pragma unroll
        for (int mf = 0; mf < 4; mf++) {
            uint32_t ad = sb + OA_H + (wm * 64 + mf * 16 + a_r) * TSTRB + kb + a_c;
            LDSM_X4(a[mf][0], a[mf][1], a[mf][2], a[mf][3], ad);
        }
        #pragma unroll
        for (int p = 0; p < 2; p++) {
            uint32_t bd = sb + OB_H + (wn * 32 + p * 16 + b_r) * TSTRB + kb + b_c;
            LDSM_X4(bhf[p][0], bhf[p][1], bhf[p][2], bhf[p][3], bd);
        }
        #pragma unroll
        for (int p = 0; p < 2; p++) {
            uint32_t bd = sb + OB_L + (wn * 32 + p * 16 + b_r) * TSTRB + kb + b_c;
            LDSM_X4(blf[p][0], blf[p][1], blf[p][2], blf[p][3], bd);
        }
        #pragma unroll
        for (int mf = 0; mf < 4; mf++)
            #pragma unroll
            for (int nf = 0; nf < 4; nf++) {
                MMA_BF16(acc[mf][nf], a[mf][0], a[mf][1], a[mf][2], a[mf][3],
                         bhf[nf >> 1][(nf & 1) * 2], bhf[nf >> 1][(nf & 1) * 2 + 1]);
                MMA_BF16(acc[mf][nf], a[mf][0], a[mf][1], a[mf][2], a[mf][3],
                         blf[nf >> 1][(nf & 1) * 2], blf[nf >> 1][(nf & 1) * 2 + 1]);
            }
        #pragma unroll
        for (int mf = 0; mf < 4; mf++) {
            uint32_t ad = sb + OA_L + (wm * 64 + mf * 16 + a_r) * TSTRB + kb + a_c;
            LDSM_X4(a[mf][0], a[mf][1], a[mf][2], a[mf][3], ad);
        }
        #pragma unroll
        for (int mf = 0; mf < 4; mf++)
            #pragma unroll
            for (int nf = 0; nf < 4; nf++)
                MMA_BF16(acc[mf][nf], a[mf][0], a[mf][1], a[mf][2], a[mf][3],
                         bhf[nf >> 1][(nf & 1) * 2], bhf[nf >> 1][(nf & 1) * 2 + 1]);
    }

    float* outp = attn + (size_t)bh * SS * SS;
    const int er = lane >> 2, ec = (lane & 3) * 2;
    #pragma unroll
    for (int mf = 0; mf < 4; mf++) {
        int r = row0 + wm * 64 + mf * 16 + er;
        #pragma unroll
        for (int nf = 0; nf < 4; nf++) {
            int c = col0 + wn * 32 + nf * 8 + ec;
            *(float2*)&outp[(size_t)r * SS + c] =
                make_float2(acc[mf][nf][0] * 0.125f, acc[mf][nf][1] * 0.125f);
            *(float2*)&outp[(size_t)(r + 8) * SS + c] =
                make_float2(acc[mf][nf][2] * 0.125f, acc[mf][nf][3] * 0.125f);
        }
    }
}

// ---------------------------------------------------------------------------
// Row softmax in place (rows of 2048), float4 I/O
// ---------------------------------------------------------------------------
__global__ __launch_bounds__(256) void softmax_kernel(float* __restrict__ attn)
{
    float4* p = (float4*)(attn + (size_t)blockIdx.x * SS);
    const int tid = threadIdx.x;
    const int w = tid >> 5, l = tid & 31;
    __shared__ float smax[8];
    __shared__ float ssum[8];
    float4 v0 = p[tid], v1 = p[tid + 256];

    float m = fmaxf(fmaxf(fmaxf(v0.x, v0.y), fmaxf(v0.z, v0.w)),
                    fmaxf(fmaxf(v1.x, v1.y), fmaxf(v1.z, v1.w)));
    #pragma unroll
    for (int o = 16; o > 0; o >>= 1) m = fmaxf(m, __shfl_xor_sync(0xffffffffu, m, o));
    if (l == 0) smax[w] = m;
    __syncthreads();
    float bm = smax[0];
    #pragma unroll
    for (int i = 1; i < 8; i++) bm = fmaxf(bm, smax[i]);

    v0.x = __expf(v0.x - bm); v0.y = __expf(v0.y - bm);
    v0.z = __expf(v0.z - bm); v0.w = __expf(v0.w - bm);
    v1.x = __expf(v1.x - bm); v1.y = __expf(v1.y - bm);
    v1.z = __expf(v1.z - bm); v1.w = __expf(v1.w - bm);
    float s = (v0.x + v0.y) + (v0.z + v0.w) + (v1.x + v1.y) + (v1.z + v1.w);
    #pragma unroll
    for (int o = 16; o > 0; o >>= 1) s += __shfl_xor_sync(0xffffffffu, s, o);
    if (l == 0) ssum[w] = s;
    __syncthreads();
    float bs = 0.f;
    #pragma unroll
    for (int i = 0; i < 8; i++) bs += ssum[i];

    const float inv = 1.0f / bs;
    v0.x *= inv; v0.y *= inv; v0.z *= inv; v0.w *= inv;
    v1.x *= inv; v1.y *= inv; v1.z *= inv; v1.w *= inv;
    p[tid] = v0;
    p[tid + 256] = v1;
}

// ---------------------------------------------------------------------------
// Context via mma.sync [R4 verbatim]: ctx -> bf16 hi/lo
// ---------------------------------------------------------------------------
#define CTX_SMEM (2 * TILE128B + 2 * TILE64B) /* 55296 */
__global__ __launch_bounds__(256) void context_mma(
    const float* __restrict__ attn,
    const __nv_bfloat16* __restrict__ vth, const __nv_bfloat16* __restrict__ vtl,
    __nv_bfloat16* __restrict__ ctxh, __nv_bfloat16* __restrict__ ctxl)
{
    extern __shared__ char smem[];
    const uint32_t sb = smem_u32(smem);
    const int tid = threadIdx.x, wid = tid >> 5, lane = tid & 31;
    const int bh = blockIdx.y, b = bh >> 3, h = bh & 7;
    const int row0 = blockIdx.x * 128;
    const uint32_t OA_H = 0, OA_L = TILE128B, OB_H = 2 * TILE128B, OB_L = 2 * TILE128B + TILE64B;

    const float* ap = attn + (size_t)bh * SS * SS;
    const __nv_bfloat16* bhp = vth + (size_t)bh * HD * SS;
    const __nv_bfloat16* blp = vtl + (size_t)bh * HD * SS;

    const int wm = wid >> 1, wn = wid & 1;
    float acc[2][4][4] = {};

    const uint32_t a_r = lane & 15, a_c = (lane >> 4) * 16;
    const uint32_t b_r = (lane & 7) + ((lane >> 4) & 1) * 8;
    const uint32_t b_c = ((lane >> 3) & 1) * 16;

    const int arow = tid >> 1, ahalf = tid & 1;
    const int brow = tid >> 2, bq = tid & 3;

    for (int t = 0; t < 32; t++) {
        __syncthreads();
        {
            const float4* src = (const float4*)(ap + (size_t)(row0 + arow) * SS + t * 64 + ahalf * 32);
            const uint32_t so = (uint32_t)arow * TSTRB + ahalf * 64;
            #pragma unroll
            for (int i = 0; i < 8; i++) {
                float4 f = src[i];
                uint32_t h0, l0, h1, l1;
                split2(f.x, f.y, h0, l0);
                split2(f.z, f.w, h1, l1);
                *(uint2*)(smem + OA_H + so + i * 8) = make_uint2(h0, h1);
                *(uint2*)(smem + OA_L + so + i * 8) = make_uint2(l0, l1);
            }
        }
        {
            size_t o = (size_t)brow * SS + t * 64 + bq * 16;
            const uint4* sh = (const uint4*)(bhp + o);
            const uint4* sl = (const uint4*)(blp + o);
            const uint32_t so = (uint32_t)brow * TSTRB + bq * 32;
            #pragma unroll
            for (int i = 0; i < 2; i++) {
                *(uint4*)(smem + OB_H + so + i * 16) = sh[i];
                *(uint4*)(smem + OB_L + so + i * 16) = sl[i];
            }
        }
        __syncthreads();
        mma_128x64_step(sb, wm, wn, a_r, a_c, b_r, b_c, acc);
    }

    const int er = lane >> 2, ec = (lane & 3) * 2;
    #pragma unroll
    for (int mf = 0; mf < 2; mf++) {
        int r = row0 + wm * 32 + mf * 16 + er;
        #pragma unroll
        for (int nf = 0; nf < 4; nf++) {
            int c = wn * 32 + nf * 8 + ec;
            uint32_t h0, l0, h1, l1;
            split2(acc[mf][nf][0], acc[mf][nf][1], h0, l0);
            split2(acc[mf][nf][2], acc[mf][nf][3], h1, l1);
            size_t o0 = (size_t)(b * SS + r) * EMBED + h * HD + c;
            size_t o1 = (size_t)(b * SS + r + 8) * EMBED + h * HD + c;
            *(uint32_t*)&ctxh[o0] = h0;
            *(uint32_t*)&ctxl[o0] = l0;
            *(uint32_t*)&ctxh[o1] = h1;
            *(uint32_t*)&ctxl[o1] = l1;
        }
    }
}

// ---------------------------------------------------------------------------
extern "C" void kernel_launch(void* const* d_in, const int* in_sizes, int n_in,
                              void* d_out, int out_size)
{
    const float* query = (const float*)d_in[0];
    const float* key   = (const float*)d_in[1];
    const float* value = (const float*)d_in[2];
    const float* Wq = (const float*)d_in[3];
    const float* bq = (const float*)d_in[4];
    const float* Wk = (const float*)d_in[5];
    const float* bk = (const float*)d_in[6];
    const float* Wv = (const float*)d_in[7];
    const float* bv = (const float*)d_in[8];
    const float* Wo = (const float*)d_in[9];
    const float* bo = (const float*)d_in[10];
    float* out = (float*)d_out;

    const size_t out_elems  = (size_t)MROWS * EMBED;
    const size_t attn_elems = (size_t)NBH * SS * SS;
    const size_t wsz = (size_t)EMBED * EMBED;

    float *pv, *pattn;
    __nv_bfloat16 *pqh, *pql, *pkh, *pkl, *pctxh, *pctxl, *pvth, *pvtl, *pwth, *pwtl;
    cudaGetSymbolAddress((void**)&pv,    g_v);
    cudaGetSymbolAddress((void**)&pattn, g_attn);
    cudaGetSymbolAddress((void**)&pqh,   g_qh);
    cudaGetSymbolAddress((void**)&pql,   g_ql);
    cudaGetSymbolAddress((void**)&pkh,   g_kh);
    cudaGetSymbolAddress((void**)&pkl,   g_kl);
    cudaGetSymbolAddress((void**)&pctxh, g_ctxh);
    cudaGetSymbolAddress((void**)&pctxl, g_ctxl);
    cudaGetSymbolAddress((void**)&pvth,  g_vth);
    cudaGetSymbolAddress((void**)&pvtl,  g_vtl);
    cudaGetSymbolAddress((void**)&pwth,  g_wth);
    cudaGetSymbolAddress((void**)&pwtl,  g_wtl);

    float* attn = ((size_t)out_size >= out_elems + attn_elems) ? (out + out_elems) : pattn;

    cudaFuncSetAttribute(proj_qkv64, cudaFuncAttributeMaxDynamicSharedMemorySize, P64_SMEM);
    cudaFuncSetAttribute(proj_out64, cudaFuncAttributeMaxDynamicSharedMemorySize, P64_SMEM);
    cudaFuncSetAttribute(scores_mma, cudaFuncAttributeMaxDynamicSharedMemorySize, SC_SMEM);
    cudaFuncSetAttribute(context_mma, cudaFuncAttributeMaxDynamicSharedMemorySize, CTX_SMEM);

    split_wT_all<<<dim3(EMBED / 32, EMBED / 32, 4), dim3(32, 8)>>>(Wq, Wk, Wv, Wo, pwth, pwtl);

    dim3 gP(EMBED / 64, MROWS / 128); // (8, 64) = 512 CTAs
    proj_qkv64<<<gP, 256, P64_SMEM>>>(query, pwth + 0 * wsz, pwtl + 0 * wsz, bq,
                                      nullptr, pqh, pql, 1);
    proj_qkv64<<<gP, 256, P64_SMEM>>>(key,   pwth + 1 * wsz, pwtl + 1 * wsz, bk,
                                      nullptr, pkh, pkl, 1);
    proj_qkv64<<<gP, 256, P64_SMEM>>>(value, pwth + 2 * wsz, pwtl + 2 * wsz, bv,
                                      pv, nullptr, nullptr, 0);

    split_vT_kernel<<<dim3(SS / 32, HD / 32, NBH), dim3(32, 8)>>>(pv, pvth, pvtl);

    scores_mma<<<dim3(SS / 128, SS / 128, NBH), 256, SC_SMEM>>>(pqh, pql, pkh, pkl, attn);

    softmax_kernel<<<NBH * SS, 256>>>(attn);

    context_mma<<<dim3(SS / 128, NBH), 256, CTX_SMEM>>>(attn, pvth, pvtl, pctxh, pctxl);

    proj_out64<<<gP, 256, P64_SMEM>>>(pctxh, pctxl, pwth + 3 * wsz, pwtl + 3 * wsz, bo, out);
}

// round 16
// speedup vs baseline: 1.0675x; 1.0675x over previous
#include <cuda_runtime.h>
#include <cuda_bf16.h>
#include <stdint.h>
#include <math.h>

#define EMBED 512
#define HEADS 8
#define HD 64
#define BB 4
#define SS 2048
#define MROWS (BB * SS) /* 8192 */
#define NBH (BB * HEADS) /* 32 */

// ------------------------- scratch (no allocs allowed) ----------------------
__device__ float g_v[(size_t)MROWS * EMBED];
__device__ float g_attn[(size_t)NBH * SS * SS];
__device__ __nv_bfloat16 g_t1h[(size_t)MROWS * EMBED];
__device__ __nv_bfloat16 g_t1l[(size_t)MROWS * EMBED];
__device__ __nv_bfloat16 g_t2h[(size_t)MROWS * EMBED];
__device__ __nv_bfloat16 g_t2l[(size_t)MROWS * EMBED];
__device__ __nv_bfloat16 g_t3h[(size_t)MROWS * EMBED];
__device__ __nv_bfloat16 g_t3l[(size_t)MROWS * EMBED];
__device__ __nv_bfloat16 g_qh[(size_t)MROWS * EMBED];
__device__ __nv_bfloat16 g_ql[(size_t)MROWS * EMBED];
__device__ __nv_bfloat16 g_kh[(size_t)MROWS * EMBED];
__device__ __nv_bfloat16 g_kl[(size_t)MROWS * EMBED];
__device__ __nv_bfloat16 g_ctxh[(size_t)MROWS * EMBED];
__device__ __nv_bfloat16 g_ctxl[(size_t)MROWS * EMBED];
__device__ __nv_bfloat16 g_vth[(size_t)NBH * HD * SS];
__device__ __nv_bfloat16 g_vtl[(size_t)NBH * HD * SS];
__device__ __nv_bfloat16 g_wth[4 * EMBED * EMBED];
__device__ __nv_bfloat16 g_wtl[4 * EMBED * EMBED];

// ------------------------- helpers -----------------------------------------
__device__ __forceinline__ uint32_t smem_u32(const void* p) {
    uint32_t a;
    asm("{ .reg .u64 t; cvta.to.shared.u64 t, %1; cvt.u32.u64 %0, t; }" : "=r"(a) : "l"(p));
    return a;
}

#define LDSM_X4(r0, r1, r2, r3, a) \
    asm volatile("ldmatrix.sync.aligned.m8n8.x4.shared.b16 {%0,%1,%2,%3}, [%4];" \
                 : "=r"(r0), "=r"(r1), "=r"(r2), "=r"(r3) : "r"(a))

#define MMA_BF16(d, a0, a1, a2, a3, b0, b1) \
    asm volatile("mma.sync.aligned.m16n8k16.row.col.f32.bf16.bf16.f32 " \
                 "{%0,%1,%2,%3}, {%4,%5,%6,%7}, {%8,%9}, {%0,%1,%2,%3};" \
                 : "+f"((d)[0]), "+f"((d)[1]), "+f"((d)[2]), "+f"((d)[3]) \
                 : "r"(a0), "r"(a1), "r"(a2), "r"(a3), "r"(b0), "r"(b1))

#define CPA16(d, s) \
    asm volatile("cp.async.cg.shared.global [%0], [%1], 16;" :: "r"(d), "l"(s))
#define CPC() asm volatile("cp.async.commit_group;" ::: "memory")
#define CPW0() asm volatile("cp.async.wait_group 0;" ::: "memory")

__device__ __forceinline__ void split2(float a, float b, uint32_t& h, uint32_t& l) {
    __nv_bfloat16 ha = __float2bfloat16(a), hb = __float2bfloat16(b);
    float la = a - __bfloat162float(ha), lb = b - __bfloat162float(hb);
    __nv_bfloat16 lla = __float2bfloat16(la), llb = __float2bfloat16(lb);
    h = ((uint32_t)__bfloat16_as_ushort(hb) << 16) | (uint32_t)__bfloat16_as_ushort(ha);
    l = ((uint32_t)__bfloat16_as_ushort(llb) << 16) | (uint32_t)__bfloat16_as_ushort(lla);
}

#define TSTRB 144
#define TILE128B (128 * TSTRB) /* 18432 */
#define TILE64B  (64 * TSTRB)  /* 9216  */
// proj double-buffer: k=32 chunks, stride 40 bf16 = 80 B
#define PSTRB 80
#define PTILEB (128 * PSTRB)   /* 10240 */
#define PSTAGE (4 * PTILEB)    /* 40960 */
#define PRJ_SMEM (2 * PSTAGE)  /* 81920 */

// ---------------------------------------------------------------------------
// Weight transpose + split (all 4 weights, one launch)
// ---------------------------------------------------------------------------
__global__ __launch_bounds__(256) void split_wT_all(
    const float* __restrict__ W0, const float* __restrict__ W1,
    const float* __restrict__ W2, const float* __restrict__ W3,
    __nv_bfloat16* __restrict__ th, __nv_bfloat16* __restrict__ tl)
{
    __shared__ float tile[32][33];
    const int z = blockIdx.z;
    const float* W = (z == 0) ? W0 : (z == 1) ? W1 : (z == 2) ? W2 : W3;
    __nv_bfloat16* tho = th + (size_t)z * EMBED * EMBED;
    __nv_bfloat16* tlo = tl + (size_t)z * EMBED * EMBED;
    const int n0 = blockIdx.x * 32, k0 = blockIdx.y * 32;
    const int tx = threadIdx.x, ty = threadIdx.y;
    #pragma unroll
    for (int j = 0; j < 4; j++)
        tile[ty + j * 8][tx] = W[(size_t)(k0 + ty + j * 8) * EMBED + n0 + tx];
    __syncthreads();
    #pragma unroll
    for (int j = 0; j < 4; j++) {
        int nl = ty + j * 8;
        float f = tile[tx][nl];
        __nv_bfloat16 hb = __float2bfloat16(f);
        __nv_bfloat16 lb = __float2bfloat16(f - __bfloat162float(hb));
        size_t o = (size_t)(n0 + nl) * EMBED + k0 + tx;
        tho[o] = hb;
        tlo[o] = lb;
    }
}

// ---------------------------------------------------------------------------
// fp32 -> bf16 hi/lo split for all 3 inputs (one launch)
// ---------------------------------------------------------------------------
__global__ __launch_bounds__(256) void split_hl_all(
    const float4* __restrict__ q, const float4* __restrict__ k, const float4* __restrict__ v,
    uint2* __restrict__ h1, uint2* __restrict__ l1,
    uint2* __restrict__ h2, uint2* __restrict__ l2,
    uint2* __restrict__ h3, uint2* __restrict__ l3, int n4)
{
    int i = blockIdx.x * 256 + threadIdx.x;
    if (i >= n4) return;
    const int y = blockIdx.y;
    const float4* x = (y == 0) ? q : (y == 1) ? k : v;
    uint2* hi = (y == 0) ? h1 : (y == 1) ? h2 : h3;
    uint2* lo = (y == 0) ? l1 : (y == 1) ? l2 : l3;
    float4 f = x[i];
    uint32_t a0, b0, a1, b1;
    split2(f.x, f.y, a0, b0);
    split2(f.z, f.w, a1, b1);
    hi[i] = make_uint2(a0, a1);
    lo[i] = make_uint2(b0, b1);
}

// ---------------------------------------------------------------------------
// V transpose + split
// ---------------------------------------------------------------------------
__global__ __launch_bounds__(256) void split_vT_kernel(
    const float* __restrict__ v, __nv_bfloat16* __restrict__ vth, __nv_bfloat16* __restrict__ vtl)
{
    __shared__ float tile[32][33];
    const int bh = blockIdx.z, b = bh >> 3, h = bh & 7;
    const int s0 = blockIdx.x * 32, d0 = blockIdx.y * 32;
    const int tx = threadIdx.x, ty = threadIdx.y;
    #pragma unroll
    for (int j = 0; j < 4; j++) {
        int sl = ty + j * 8;
        tile[sl][tx] = v[(size_t)(b * SS + s0 + sl) * EMBED + h * HD + d0 + tx];
    }
    __syncthreads();
    #pragma unroll
    for (int j = 0; j < 4; j++) {
        int dl = ty + j * 8;
        float f = tile[tx][dl];
        __nv_bfloat16 hb = __float2bfloat16(f);
        __nv_bfloat16 lb = __float2bfloat16(f - __bfloat162float(hb));
        size_t o = ((size_t)bh * HD + d0 + dl) * SS + s0 + tx;
        vth[o] = hb;
        vtl[o] = lb;
    }
}

// ---------------------------------------------------------------------------
// Projection GEMM, cp.async double-buffered, k-chunks of 32 (R5 version).
// 128x128 tile, warps 2x4 (64x32 each). regs cap 2 CTA/SM; smem 81.9KB = 2 CTA/SM.
// ---------------------------------------------------------------------------
__global__ __launch_bounds__(256) void proj_mma(
    const __nv_bfloat16* __restrict__ ah, const __nv_bfloat16* __restrict__ al,
    const __nv_bfloat16* __restrict__ wth, const __nv_bfloat16* __restrict__ wtl,
    const float* __restrict__ bias,
    float* __restrict__ cf, __nv_bfloat16* __restrict__ ch, __nv_bfloat16* __restrict__ cl,
    int mode)
{
    extern __shared__ char smem[];
    const uint32_t sb = smem_u32(smem);
    const int tid = threadIdx.x, wid = tid >> 5, lane = tid & 31;
    const int row0 = blockIdx.y * 128, col0 = blockIdx.x * 128;

    const int wm = wid >> 2, wn = wid & 3;
    float acc[4][4][4] = {};

    const uint32_t a_r = lane & 15, a_c = (lane >> 4) * 16;
    const uint32_t b_r = (lane & 7) + ((lane >> 4) & 1) * 8;
    const uint32_t b_c = ((lane >> 3) & 1) * 16;

    const int c0 = tid * 2;
    const int lr0 = c0 >> 2, lq0 = (c0 & 3);
    const int lr1 = (c0 + 1) >> 2, lq1 = ((c0 + 1) & 3);

    {
        const uint32_t st = sb;
        CPA16(st + 0 * PTILEB + lr0 * PSTRB + lq0 * 16, ah + (size_t)(row0 + lr0) * EMBED + lq0 * 8);
        CPA16(st + 0 * PTILEB + lr1 * PSTRB + lq1 * 16, ah + (size_t)(row0 + lr1) * EMBED + lq1 * 8);
        CPA16(st + 1 * PTILEB + lr0 * PSTRB + lq0 * 16, al + (size_t)(row0 + lr0) * EMBED + lq0 * 8);
        CPA16(st + 1 * PTILEB + lr1 * PSTRB + lq1 * 16, al + (size_t)(row0 + lr1) * EMBED + lq1 * 8);
        CPA16(st + 2 * PTILEB + lr0 * PSTRB + lq0 * 16, wth + (size_t)(col0 + lr0) * EMBED + lq0 * 8);
        CPA16(st + 2 * PTILEB + lr1 * PSTRB + lq1 * 16, wth + (size_t)(col0 + lr1) * EMBED + lq1 * 8);
        CPA16(st + 3 * PTILEB + lr0 * PSTRB + lq0 * 16, wtl + (size_t)(col0 + lr0) * EMBED + lq0 * 8);
        CPA16(st + 3 * PTILEB + lr1 * PSTRB + lq1 * 16, wtl + (size_t)(col0 + lr1) * EMBED + lq1 * 8);
        CPC();
    }

    for (int it = 0; it < 16; it++) {
        CPW0();
        __syncthreads();
        if (it < 15) {
            const int kc = (it + 1) * 32;
            const uint32_t st = sb + ((it + 1) & 1) * PSTAGE;
            CPA16(st + 0 * PTILEB + lr0 * PSTRB + lq0 * 16, ah + (size_t)(row0 + lr0) * EMBED + kc + lq0 * 8);
            CPA16(st + 0 * PTILEB + lr1 * PSTRB + lq1 * 16, ah + (size_t)(row0 + lr1) * EMBED + kc + lq1 * 8);
            CPA16(st + 1 * PTILEB + lr0 * PSTRB + lq0 * 16, al + (size_t)(row0 + lr0) * EMBED + kc + lq0 * 8);
            CPA16(st + 1 * PTILEB + lr1 * PSTRB + lq1 * 16, al + (size_t)(row0 + lr1) * EMBED + kc + lq1 * 8);
            CPA16(st + 2 * PTILEB + lr0 * PSTRB + lq0 * 16, wth + (size_t)(col0 + lr0) * EMBED + kc + lq0 * 8);
            CPA16(st + 2 * PTILEB + lr1 * PSTRB + lq1 * 16, wth + (size_t)(col0 + lr1) * EMBED + kc + lq1 * 8);
            CPA16(st + 3 * PTILEB + lr0 * PSTRB + lq0 * 16, wtl + (size_t)(col0 + lr0) * EMBED + kc + lq0 * 8);
            CPA16(st + 3 * PTILEB + lr1 * PSTRB + lq1 * 16, wtl + (size_t)(col0 + lr1) * EMBED + kc + lq1 * 8);
            CPC();
        }
        const uint32_t base = sb + (it & 1) * PSTAGE;
        #pragma unroll
        for (int ks = 0; ks < 2; ks++) {
            const uint32_t kb = ks * 32;
            uint32_t a[4][4], bhf[2][4], blf[2][4];
            #pragma unroll
            for (int mf = 0; mf < 4; mf++) {
                uint32_t ad = base + 0 * PTILEB + (wm * 64 + mf * 16 + a_r) * PSTRB + kb + a_c;
                LDSM_X4(a[mf][0], a[mf][1], a[mf][2], a[mf][3], ad);
            }
            #pragma unroll
            for (int p = 0; p < 2; p++) {
                uint32_t bd = base + 2 * PTILEB + (wn * 32 + p * 16 + b_r) * PSTRB + kb + b_c;
                LDSM_X4(bhf[p][0], bhf[p][1], bhf[p][2], bhf[p][3], bd);
            }
            #pragma unroll
            for (int p = 0; p < 2; p++) {
                uint32_t bd = base + 3 * PTILEB + (wn * 32 + p * 16 + b_r) * PSTRB + kb + b_c;
                LDSM_X4(blf[p][0], blf[p][1], blf[p][2], blf[p][3], bd);
            }
            #pragma unroll
            for (int mf = 0; mf < 4; mf++)
                #pragma unroll
                for (int nf = 0; nf < 4; nf++) {
                    MMA_BF16(acc[mf][nf], a[mf][0], a[mf][1], a[mf][2], a[mf][3],
                             bhf[nf >> 1][(nf & 1) * 2], bhf[nf >> 1][(nf & 1) * 2 + 1]);
                    MMA_BF16(acc[mf][nf], a[mf][0], a[mf][1], a[mf][2], a[mf][3],
                             blf[nf >> 1][(nf & 1) * 2], blf[nf >> 1][(nf & 1) * 2 + 1]);
                }
            #pragma unroll
            for (int mf = 0; mf < 4; mf++) {
                uint32_t ad = base + 1 * PTILEB + (wm * 64 + mf * 16 + a_r) * PSTRB + kb + a_c;
                LDSM_X4(a[mf][0], a[mf][1], a[mf][2], a[mf][3], ad);
            }
            #pragma unroll
            for (int mf = 0; mf < 4; mf++)
                #pragma unroll
                for (int nf = 0; nf < 4; nf++)
                    MMA_BF16(acc[mf][nf], a[mf][0], a[mf][1], a[mf][2], a[mf][3],
                             bhf[nf >> 1][(nf & 1) * 2], bhf[nf >> 1][(nf & 1) * 2 + 1]);
        }
    }

    const int er = lane >> 2, ec = (lane & 3) * 2;
    #pragma unroll
    for (int mf = 0; mf < 4; mf++) {
        int r = row0 + wm * 64 + mf * 16 + er;
        #pragma unroll
        for (int nf = 0; nf < 4; nf++) {
            int c = col0 + wn * 32 + nf * 8 + ec;
            float b0 = bias[c], b1 = bias[c + 1];
            float v00 = acc[mf][nf][0] + b0, v01 = acc[mf][nf][1] + b1;
            float v10 = acc[mf][nf][2] + b0, v11 = acc[mf][nf][3] + b1;
            if (mode == 0) {
                *(float2*)&cf[(size_t)r * EMBED + c] = make_float2(v00, v01);
                *(float2*)&cf[(size_t)(r + 8) * EMBED + c] = make_float2(v10, v11);
            } else {
                uint32_t h0, l0, h1, l1;
                split2(v00, v01, h0, l0);
                split2(v10, v11, h1, l1);
                *(uint32_t*)&ch[(size_t)r * EMBED + c] = h0;
                *(uint32_t*)&cl[(size_t)r * EMBED + c] = l0;
                *(uint32_t*)&ch[(size_t)(r + 8) * EMBED + c] = h1;
                *(uint32_t*)&cl[(size_t)(r + 8) * EMBED + c] = l1;
            }
        }
    }
}

// ---------------------------------------------------------------------------
// Scores via mma.sync [R4 verbatim]
// ---------------------------------------------------------------------------
#define SC_SMEM (4 * TILE128B) /* 73728 */
__global__ __launch_bounds__(256) void scores_mma(
    const __nv_bfloat16* __restrict__ qh, const __nv_bfloat16* __restrict__ ql,
    const __nv_bfloat16* __restrict__ kh, const __nv_bfloat16* __restrict__ kl,
    float* __restrict__ attn)
{
    extern __shared__ char smem[];
    const uint32_t sb = smem_u32(smem);
    const int tid = threadIdx.x, wid = tid >> 5, lane = tid & 31;
    const int bh = blockIdx.z, b = bh >> 3, h = bh & 7;
    const int row0 = blockIdx.y * 128, col0 = blockIdx.x * 128;
    const uint32_t OA_H = 0, OA_L = TILE128B, OB_H = 2 * TILE128B, OB_L = 3 * TILE128B;

    {
        const int lrow = tid >> 1, lhalf = tid & 1;
        size_t qo = (size_t)(b * SS + row0 + lrow) * EMBED + h * HD + lhalf * 32;
        size_t ko = (size_t)(b * SS + col0 + lrow) * EMBED + h * HD + lhalf * 32;
        const uint4* qhp = (const uint4*)(qh + qo);
        const uint4* qlp = (const uint4*)(ql + qo);
        const uint4* khp = (const uint4*)(kh + ko);
        const uint4* klp = (const uint4*)(kl + ko);
        const uint32_t so = (uint32_t)lrow * TSTRB + lhalf * 64;
        #pragma unroll
        for (int i = 0; i < 4; i++) {
            *(uint4*)(smem + OA_H + so + i * 16) = qhp[i];
            *(uint4*)(smem + OA_L + so + i * 16) = qlp[i];
            *(uint4*)(smem + OB_H + so + i * 16) = khp[i];
            *(uint4*)(smem + OB_L + so + i * 16) = klp[i];
        }
    }
    __syncthreads();

    const int wm = wid >> 2, wn = wid & 3;
    float acc[4][4][4] = {};
    const uint32_t a_r = lane & 15, a_c = (lane >> 4) * 16;
    const uint32_t b_r = (lane & 7) + ((lane >> 4) & 1) * 8;
    const uint32_t b_c = ((lane >> 3) & 1) * 16;

    #pragma unroll
    for (int ks = 0; ks < 4; ks++) {
        const uint32_t kb = ks * 32;
        uint32_t a[4][4], bhf[2][4], blf[2][4];
        #pragma unroll
        for (int mf = 0; mf < 4; mf++) {
            uint32_t ad = sb + OA_H + (wm * 64 + mf * 16 + a_r) * TSTRB + kb + a_c;
            LDSM_X4(a[mf][0], a[mf][1], a[mf][2], a[mf][3], ad);
        }
        #pragma unroll
        for (int p = 0; p < 2; p++) {
            uint32_t bd = sb + OB_H + (wn * 32 + p * 16 + b_r) * TSTRB + kb + b_c;
            LDSM_X4(bhf[p][0], bhf[p][1], bhf[p][2], bhf[p][3], bd);
        }
        #pragma unroll
        for (int p = 0; p < 2; p++) {
            uint32_t bd = sb + OB_L + (wn * 32 + p * 16 + b_r) * TSTRB + kb + b_c;
            LDSM_X4(blf[p][0], blf[p][1], blf[p][2], blf[p][3], bd);
        }
        #pragma unroll
        for (int mf = 0; mf < 4; mf++)
            #pragma unroll
            for (int nf = 0; nf < 4; nf++) {
                MMA_BF16(acc[mf][nf], a[mf][0], a[mf][1], a[mf][2], a[mf][3],
                         bhf[nf >> 1][(nf & 1) * 2], bhf[nf >> 1][(nf & 1) * 2 + 1]);
                MMA_BF16(acc[mf][nf], a[mf][0], a[mf][1], a[mf][2], a[mf][3],
                         blf[nf >> 1][(nf & 1) * 2], blf[nf >> 1][(nf & 1) * 2 + 1]);
            }
        #pragma unroll
        for (int mf = 0; mf < 4; mf++) {
            uint32_t ad = sb + OA_L + (wm * 64 + mf * 16 + a_r) * TSTRB + kb + a_c;
            LDSM_X4(a[mf][0], a[mf][1], a[mf][2], a[mf][3], ad);
        }
        #pragma unroll
        for (int mf = 0; mf < 4; mf++)
            #pragma unroll
            for (int nf = 0; nf < 4; nf++)
                MMA_BF16(acc[mf][nf], a[mf][0], a[mf][1], a[mf][2], a[mf][3],
                         bhf[nf >> 1][(nf & 1) * 2], bhf[nf >> 1][(nf & 1) * 2 + 1]);
    }

    float* outp = attn + (size_t)bh * SS * SS;
    const int er = lane >> 2, ec = (lane & 3) * 2;
    #pragma unroll
    for (int mf = 0; mf < 4; mf++) {
        int r = row0 + wm * 64 + mf * 16 + er;
        #pragma unroll
        for (int nf = 0; nf < 4; nf++) {
            int c = col0 + wn * 32 + nf * 8 + ec;
            *(float2*)&outp[(size_t)r * SS + c] =
                make_float2(acc[mf][nf][0] * 0.125f, acc[mf][nf][1] * 0.125f);
            *(float2*)&outp[(size_t)(r + 8) * SS + c] =
                make_float2(acc[mf][nf][2] * 0.125f, acc[mf][nf][3] * 0.125f);
        }
    }
}

// ---------------------------------------------------------------------------
// Row softmax in place (rows of 2048), float4 I/O
// ---------------------------------------------------------------------------
__global__ __launch_bounds__(256) void softmax_kernel(float* __restrict__ attn)
{
    float4* p = (float4*)(attn + (size_t)blockIdx.x * SS);
    const int tid = threadIdx.x;
    const int w = tid >> 5, l = tid & 31;
    __shared__ float smax[8];
    __shared__ float ssum[8];
    float4 v0 = p[tid], v1 = p[tid + 256];

    float m = fmaxf(fmaxf(fmaxf(v0.x, v0.y), fmaxf(v0.z, v0.w)),
                    fmaxf(fmaxf(v1.x, v1.y), fmaxf(v1.z, v1.w)));
    #pragma unroll
    for (int o = 16; o > 0; o >>= 1) m = fmaxf(m, __shfl_xor_sync(0xffffffffu, m, o));
    if (l == 0) smax[w] = m;
    __syncthreads();
    float bm = smax[0];
    #pragma unroll
    for (int i = 1; i < 8; i++) bm = fmaxf(bm, smax[i]);

    v0.x = __expf(v0.x - bm); v0.y = __expf(v0.y - bm);
    v0.z = __expf(v0.z - bm); v0.w = __expf(v0.w - bm);
    v1.x = __expf(v1.x - bm); v1.y = __expf(v1.y - bm);
    v1.z = __expf(v1.z - bm); v1.w = __expf(v1.w - bm);
    float s = (v0.x + v0.y) + (v0.z + v0.w) + (v1.x + v1.y) + (v1.z + v1.w);
    #pragma unroll
    for (int o = 16; o > 0; o >>= 1) s += __shfl_xor_sync(0xffffffffu, s, o);
    if (l == 0) ssum[w] = s;
    __syncthreads();
    float bs = 0.f;
    #pragma unroll
    for (int i = 0; i < 8; i++) bs += ssum[i];

    const float inv = 1.0f / bs;
    v0.x *= inv; v0.y *= inv; v0.z *= inv; v0.w *= inv;
    v1.x *= inv; v1.y *= inv; v1.z *= inv; v1.w *= inv;
    p[tid] = v0;
    p[tid + 256] = v1;
}

// ---------------------------------------------------------------------------
// Context via mma.sync [R4 verbatim]: ctx -> bf16 hi/lo
// ---------------------------------------------------------------------------
#define CTX_SMEM (2 * TILE128B + 2 * TILE64B) /* 55296 */
__global__ __launch_bounds__(256) void context_mma(
    const float* __restrict__ attn,
    const __nv_bfloat16* __restrict__ vth, const __nv_bfloat16* __restrict__ vtl,
    __nv_bfloat16* __restrict__ ctxh, __nv_bfloat16* __restrict__ ctxl)
{
    extern __shared__ char smem[];
    const uint32_t sb = smem_u32(smem);
    const int tid = threadIdx.x, wid = tid >> 5, lane = tid & 31;
    const int bh = blockIdx.y, b = bh >> 3, h = bh & 7;
    const int row0 = blockIdx.x * 128;
    const uint32_t OA_H = 0, OA_L = TILE128B, OB_H = 2 * TILE128B, OB_L = 2 * TILE128B + TILE64B;

    const float* ap = attn + (size_t)bh * SS * SS;
    const __nv_bfloat16* bhp = vth + (size_t)bh * HD * SS;
    const __nv_bfloat16* blp = vtl + (size_t)bh * HD * SS;

    const int wm = wid >> 1, wn = wid & 1;
    float acc[2][4][4] = {};

    const uint32_t a_r = lane & 15, a_c = (lane >> 4) * 16;
    const uint32_t b_r = (lane & 7) + ((lane >> 4) & 1) * 8;
    const uint32_t b_c = ((lane >> 3) & 1) * 16;

    const int arow = tid >> 1, ahalf = tid & 1;
    const int brow = tid >> 2, bq = tid & 3;

    for (int t = 0; t < 32; t++) {
        __syncthreads();
        {
            const float4* src = (const float4*)(ap + (size_t)(row0 + arow) * SS + t * 64 + ahalf * 32);
            const uint32_t so = (uint32_t)arow * TSTRB + ahalf * 64;
            #pragma unroll
            for (int i = 0; i < 8; i++) {
                float4 f = src[i];
                uint32_t h0, l0, h1, l1;
                split2(f.x, f.y, h0, l0);
                split2(f.z, f.w, h1, l1);
                *(uint2*)(smem + OA_H + so + i * 8) = make_uint2(h0, h1);
                *(uint2*)(smem + OA_L + so + i * 8) = make_uint2(l0, l1);
            }
        }
        {
            size_t o = (size_t)brow * SS + t * 64 + bq * 16;
            const uint4* sh = (const uint4*)(bhp + o);
            const uint4* sl = (const uint4*)(blp + o);
            const uint32_t so = (uint32_t)brow * TSTRB + bq * 32;
            #pragma unroll
            for (int i = 0; i < 2; i++) {
                *(uint4*)(smem + OB_H + so + i * 16) = sh[i];
                *(uint4*)(smem + OB_L + so + i * 16) = sl[i];
            }
        }
        __syncthreads();

        #pragma unroll
        for (int ks = 0; ks < 4; ks++) {
            const uint32_t kb = ks * 32;
            uint32_t a[2][4], bhf[2][4], blf[2][4];
            #pragma unroll
            for (int mf = 0; mf < 2; mf++) {
                uint32_t ad = sb + OA_H + (wm * 32 + mf * 16 + a_r) * TSTRB + kb + a_c;
                LDSM_X4(a[mf][0], a[mf][1], a[mf][2], a[mf][3], ad);
            }
            #pragma unroll
            for (int p = 0; p < 2; p++) {
                uint32_t bd = sb + OB_H + (wn * 32 + p * 16 + b_r) * TSTRB + kb + b_c;
                LDSM_X4(bhf[p][0], bhf[p][1], bhf[p][2], bhf[p][3], bd);
            }
            #pragma unroll
            for (int p = 0; p < 2; p++) {
                uint32_t bd = sb + OB_L + (wn * 32 + p * 16 + b_r) * TSTRB + kb + b_c;
                LDSM_X4(blf[p][0], blf[p][1], blf[p][2], blf[p][3], bd);
            }
            #pragma unroll
            for (int mf = 0; mf < 2; mf++)
                #pragma unroll
                for (int nf = 0; nf < 4; nf++) {
                    MMA_BF16(acc[mf][nf], a[mf][0], a[mf][1], a[mf][2], a[mf][3],
                             bhf[nf >> 1][(nf & 1) * 2], bhf[nf >> 1][(nf & 1) * 2 + 1]);
                    MMA_BF16(acc[mf][nf], a[mf][0], a[mf][1], a[mf][2], a[mf][3],
                             blf[nf >> 1][(nf & 1) * 2], blf[nf >> 1][(nf & 1) * 2 + 1]);
                }
            #pragma unroll
            for (int mf = 0; mf < 2; mf++) {
                uint32_t ad = sb + OA_L + (wm * 32 + mf * 16 + a_r) * TSTRB + kb + a_c;
                LDSM_X4(a[mf][0], a[mf][1], a[mf][2], a[mf][3], ad);
            }
            #pragma unroll
            for (int mf = 0; mf < 2; mf++)
                #pragma unroll
                for (int nf = 0; nf < 4; nf++)
                    MMA_BF16(acc[mf][nf], a[mf][0], a[mf][1], a[mf][2], a[mf][3],
                             bhf[nf >> 1][(nf & 1) * 2], bhf[nf >> 1][(nf & 1) * 2 + 1]);
        }
    }

    const int er = lane >> 2, ec = (lane & 3) * 2;
    #pragma unroll
    for (int mf = 0; mf < 2; mf++) {
        int r = row0 + wm * 32 + mf * 16 + er;
        #pragma unroll
        for (int nf = 0; nf < 4; nf++) {
            int c = wn * 32 + nf * 8 + ec;
            uint32_t h0, l0, h1, l1;
            split2(acc[mf][nf][0], acc[mf][nf][1], h0, l0);
            split2(acc[mf][nf][2], acc[mf][nf][3], h1, l1);
            size_t o0 = (size_t)(b * SS + r) * EMBED + h * HD + c;
            size_t o1 = (size_t)(b * SS + r + 8) * EMBED + h * HD + c;
            *(uint32_t*)&ctxh[o0] = h0;
            *(uint32_t*)&ctxl[o0] = l0;
            *(uint32_t*)&ctxh[o1] = h1;
            *(uint32_t*)&ctxl[o1] = l1;
        }
    }
}

// ---------------------------------------------------------------------------
extern "C" void kernel_launch(void* const* d_in, const int* in_sizes, int n_in,
                              void* d_out, int out_size)
{
    const float* query = (const float*)d_in[0];
    const float* key   = (const float*)d_in[1];
    const float* value = (const float*)d_in[2];
    const float* Wq = (const float*)d_in[3];
    const float* bq = (const float*)d_in[4];
    const float* Wk = (const float*)d_in[5];
    const float* bk = (const float*)d_in[6];
    const float* Wv = (const float*)d_in[7];
    const float* bv = (const float*)d_in[8];
    const float* Wo = (const float*)d_in[9];
    const float* bo = (const float*)d_in[10];
    float* out = (float*)d_out;

    const size_t out_elems  = (size_t)MROWS * EMBED;
    const size_t attn_elems = (size_t)NBH * SS * SS;
    const size_t wsz = (size_t)EMBED * EMBED;

    float *pv, *pattn;
    __nv_bfloat16 *pt1h, *pt1l, *pt2h, *pt2l, *pt3h, *pt3l;
    __nv_bfloat16 *pqh, *pql, *pkh, *pkl, *pctxh, *pctxl, *pvth, *pvtl, *pwth, *pwtl;
    cudaGetSymbolAddress((void**)&pv,    g_v);
    cudaGetSymbolAddress((void**)&pattn, g_attn);
    cudaGetSymbolAddress((void**)&pt1h,  g_t1h);
    cudaGetSymbolAddress((void**)&pt1l,  g_t1l);
    cudaGetSymbolAddress((void**)&pt2h,  g_t2h);
    cudaGetSymbolAddress((void**)&pt2l,  g_t2l);
    cudaGetSymbolAddress((void**)&pt3h,  g_t3h);
    cudaGetSymbolAddress((void**)&pt3l,  g_t3l);
    cudaGetSymbolAddress((void**)&pqh,   g_qh);
    cudaGetSymbolAddress((void**)&pql,   g_ql);
    cudaGetSymbolAddress((void**)&pkh,   g_kh);
    cudaGetSymbolAddress((void**)&pkl,   g_kl);
    cudaGetSymbolAddress((void**)&pctxh, g_ctxh);
    cudaGetSymbolAddress((void**)&pctxl, g_ctxl);
    cudaGetSymbolAddress((void**)&pvth,  g_vth);
    cudaGetSymbolAddress((void**)&pvtl,  g_vtl);
    cudaGetSymbolAddress((void**)&pwth,  g_wth);
    cudaGetSymbolAddress((void**)&pwtl,  g_wtl);

    float* attn = ((size_t)out_size >= out_elems + attn_elems) ? (out + out_elems) : pattn;

    cudaFuncSetAttribute(proj_mma, cudaFuncAttributeMaxDynamicSharedMemorySize, PRJ_SMEM);
    cudaFuncSetAttribute(scores_mma, cudaFuncAttributeMaxDynamicSharedMemorySize, SC_SMEM);
    cudaFuncSetAttribute(context_mma, cudaFuncAttributeMaxDynamicSharedMemorySize, CTX_SMEM);

    split_wT_all<<<dim3(EMBED / 32, EMBED / 32, 4), dim3(32, 8)>>>(Wq, Wk, Wv, Wo, pwth, pwtl);

    const int n4 = (MROWS * EMBED) / 4;
    split_hl_all<<<dim3(n4 / 256, 3), 256>>>(
        (const float4*)query, (const float4*)key, (const float4*)value,
        (uint2*)pt1h, (uint2*)pt1l, (uint2*)pt2h, (uint2*)pt2l, (uint2*)pt3h, (uint2*)pt3l, n4);

    dim3 gP(EMBED / 128, MROWS / 128);
    proj_mma<<<gP, 256, PRJ_SMEM>>>(pt1h, pt1l, pwth + 0 * wsz, pwtl + 0 * wsz, bq,
                                    nullptr, pqh, pql, 1);
    proj_mma<<<gP, 256, PRJ_SMEM>>>(pt2h, pt2l, pwth + 1 * wsz, pwtl + 1 * wsz, bk,
                                    nullptr, pkh, pkl, 1);
    proj_mma<<<gP, 256, PRJ_SMEM>>>(pt3h, pt3l, pwth + 2 * wsz, pwtl + 2 * wsz, bv,
                                    pv, nullptr, nullptr, 0);

    split_vT_kernel<<<dim3(SS / 32, HD / 32, NBH), dim3(32, 8)>>>(pv, pvth, pvtl);

    scores_mma<<<dim3(SS / 128, SS / 128, NBH), 256, SC_SMEM>>>(pqh, pql, pkh, pkl, attn);

    softmax_kernel<<<NBH * SS, 256>>>(attn);

    context_mma<<<dim3(SS / 128, NBH), 256, CTX_SMEM>>>(attn, pvth, pvtl, pctxh, pctxl);

    proj_mma<<<gP, 256, PRJ_SMEM>>>(pctxh, pctxl, pwth + 3 * wsz, pwtl + 3 * wsz, bo,
                                    out, nullptr, nullptr, 0);
}

// round 17
// speedup vs baseline: 1.0846x; 1.0160x over previous
#include <cuda_runtime.h>
#include <cuda_bf16.h>
#include <stdint.h>
#include <math.h>

#define EMBED 512
#define HEADS 8
#define HD 64
#define BB 4
#define SS 2048
#define MROWS (BB * SS) /* 8192 */
#define NBH (BB * HEADS) /* 32 */

// ------------------------- scratch (no allocs allowed) ----------------------
__device__ float g_v[(size_t)MROWS * EMBED];
__device__ float g_attn[(size_t)NBH * SS * SS];
__device__ __nv_bfloat16 g_t1h[(size_t)MROWS * EMBED];
__device__ __nv_bfloat16 g_t1l[(size_t)MROWS * EMBED];
__device__ __nv_bfloat16 g_t2h[(size_t)MROWS * EMBED];
__device__ __nv_bfloat16 g_t2l[(size_t)MROWS * EMBED];
__device__ __nv_bfloat16 g_t3h[(size_t)MROWS * EMBED];
__device__ __nv_bfloat16 g_t3l[(size_t)MROWS * EMBED];
__device__ __nv_bfloat16 g_qh[(size_t)MROWS * EMBED];
__device__ __nv_bfloat16 g_ql[(size_t)MROWS * EMBED];
__device__ __nv_bfloat16 g_kh[(size_t)MROWS * EMBED];
__device__ __nv_bfloat16 g_kl[(size_t)MROWS * EMBED];
__device__ __nv_bfloat16 g_ctxh[(size_t)MROWS * EMBED];
__device__ __nv_bfloat16 g_ctxl[(size_t)MROWS * EMBED];
__device__ __nv_bfloat16 g_vth[(size_t)NBH * HD * SS];
__device__ __nv_bfloat16 g_vtl[(size_t)NBH * HD * SS];
__device__ __nv_bfloat16 g_wth[4 * EMBED * EMBED];
__device__ __nv_bfloat16 g_wtl[4 * EMBED * EMBED];

// ------------------------- helpers -----------------------------------------
__device__ __forceinline__ uint32_t smem_u32(const void* p) {
    uint32_t a;
    asm("{ .reg .u64 t; cvta.to.shared.u64 t, %1; cvt.u32.u64 %0, t; }" : "=r"(a) : "l"(p));
    return a;
}

#define LDSM_X4(r0, r1, r2, r3, a) \
    asm volatile("ldmatrix.sync.aligned.m8n8.x4.shared.b16 {%0,%1,%2,%3}, [%4];" \
                 : "=r"(r0), "=r"(r1), "=r"(r2), "=r"(r3) : "r"(a))

#define MMA_BF16(d, a0, a1, a2, a3, b0, b1) \
    asm volatile("mma.sync.aligned.m16n8k16.row.col.f32.bf16.bf16.f32 " \
                 "{%0,%1,%2,%3}, {%4,%5,%6,%7}, {%8,%9}, {%0,%1,%2,%3};" \
                 : "+f"((d)[0]), "+f"((d)[1]), "+f"((d)[2]), "+f"((d)[3]) \
                 : "r"(a0), "r"(a1), "r"(a2), "r"(a3), "r"(b0), "r"(b1))

__device__ __forceinline__ void split2(float a, float b, uint32_t& h, uint32_t& l) {
    __nv_bfloat16 ha = __float2bfloat16(a), hb = __float2bfloat16(b);
    float la = a - __bfloat162float(ha), lb = b - __bfloat162float(hb);
    __nv_bfloat16 lla = __float2bfloat16(la), llb = __float2bfloat16(lb);
    h = ((uint32_t)__bfloat16_as_ushort(hb) << 16) | (uint32_t)__bfloat16_as_ushort(ha);
    l = ((uint32_t)__bfloat16_as_ushort(llb) << 16) | (uint32_t)__bfloat16_as_ushort(lla);
}

#define TSTRB 144
#define TILE128B (128 * TSTRB) /* 18432 */
#define TILE64B  (64 * TSTRB)  /* 9216  */

// ---------------------------------------------------------------------------
// Weight transpose + split (all 4 weights in one launch; z selects matrix)
// ---------------------------------------------------------------------------
__global__ __launch_bounds__(256) void split_wT_all(
    const float* __restrict__ W0, const float* __restrict__ W1,
    const float* __restrict__ W2, const float* __restrict__ W3,
    __nv_bfloat16* __restrict__ th, __nv_bfloat16* __restrict__ tl)
{
    __shared__ float tile[32][33];
    const int z = blockIdx.z;
    const float* W = (z == 0) ? W0 : (z == 1) ? W1 : (z == 2) ? W2 : W3;
    __nv_bfloat16* tho = th + (size_t)z * EMBED * EMBED;
    __nv_bfloat16* tlo = tl + (size_t)z * EMBED * EMBED;
    const int n0 = blockIdx.x * 32, k0 = blockIdx.y * 32;
    const int tx = threadIdx.x, ty = threadIdx.y;
    #pragma unroll
    for (int j = 0; j < 4; j++)
        tile[ty + j * 8][tx] = W[(size_t)(k0 + ty + j * 8) * EMBED + n0 + tx];
    __syncthreads();
    #pragma unroll
    for (int j = 0; j < 4; j++) {
        int nl = ty + j * 8;
        float f = tile[tx][nl];
        __nv_bfloat16 hb = __float2bfloat16(f);
        __nv_bfloat16 lb = __float2bfloat16(f - __bfloat162float(hb));
        size_t o = (size_t)(n0 + nl) * EMBED + k0 + tx;
        tho[o] = hb;
        tlo[o] = lb;
    }
}

// ---------------------------------------------------------------------------
// fp32 -> bf16 hi/lo split for all 3 inputs in one launch (y selects input)
// ---------------------------------------------------------------------------
__global__ __launch_bounds__(256) void split_hl_all(
    const float4* __restrict__ q, const float4* __restrict__ k, const float4* __restrict__ v,
    uint2* __restrict__ h1, uint2* __restrict__ l1,
    uint2* __restrict__ h2, uint2* __restrict__ l2,
    uint2* __restrict__ h3, uint2* __restrict__ l3, int n4)
{
    int i = blockIdx.x * 256 + threadIdx.x;
    if (i >= n4) return;
    const int y = blockIdx.y;
    const float4* x = (y == 0) ? q : (y == 1) ? k : v;
    uint2* hi = (y == 0) ? h1 : (y == 1) ? h2 : h3;
    uint2* lo = (y == 0) ? l1 : (y == 1) ? l2 : l3;
    float4 f = x[i];
    uint32_t a0, b0, a1, b1;
    split2(f.x, f.y, a0, b0);
    split2(f.z, f.w, a1, b1);
    hi[i] = make_uint2(a0, a1);
    lo[i] = make_uint2(b0, b1);
}

// ---------------------------------------------------------------------------
// V transpose + split
// ---------------------------------------------------------------------------
__global__ __launch_bounds__(256) void split_vT_kernel(
    const float* __restrict__ v, __nv_bfloat16* __restrict__ vth, __nv_bfloat16* __restrict__ vtl)
{
    __shared__ float tile[32][33];
    const int bh = blockIdx.z, b = bh >> 3, h = bh & 7;
    const int s0 = blockIdx.x * 32, d0 = blockIdx.y * 32;
    const int tx = threadIdx.x, ty = threadIdx.y;
    #pragma unroll
    for (int j = 0; j < 4; j++) {
        int sl = ty + j * 8;
        tile[sl][tx] = v[(size_t)(b * SS + s0 + sl) * EMBED + h * HD + d0 + tx];
    }
    __syncthreads();
    #pragma unroll
    for (int j = 0; j < 4; j++) {
        int dl = ty + j * 8;
        float f = tile[tx][dl];
        __nv_bfloat16 hb = __float2bfloat16(f);
        __nv_bfloat16 lb = __float2bfloat16(f - __bfloat162float(hb));
        size_t o = ((size_t)bh * HD + d0 + dl) * SS + s0 + tx;
        vth[o] = hb;
        vtl[o] = lb;
    }
}

// ---------------------------------------------------------------------------
// Projection GEMM via mma.sync, split-bf16, K=512 (3 CTAs/SM). [R4/R11 verbatim]
// ---------------------------------------------------------------------------
#define PRJ_SMEM (4 * TILE128B) /* 73728 */
__global__ __launch_bounds__(256) void proj_mma(
    const __nv_bfloat16* __restrict__ ah, const __nv_bfloat16* __restrict__ al,
    const __nv_bfloat16* __restrict__ wth, const __nv_bfloat16* __restrict__ wtl,
    const float* __restrict__ bias,
    float* __restrict__ cf, __nv_bfloat16* __restrict__ ch, __nv_bfloat16* __restrict__ cl,
    int mode)
{
    extern __shared__ char smem[];
    const uint32_t sb = smem_u32(smem);
    const int tid = threadIdx.x, wid = tid >> 5, lane = tid & 31;
    const int row0 = blockIdx.y * 128, col0 = blockIdx.x * 128;
    const uint32_t OA_H = 0, OA_L = TILE128B, OB_H = 2 * TILE128B, OB_L = 3 * TILE128B;

    const int wm = wid >> 2, wn = wid & 3;
    float acc[4][4][4] = {};

    const uint32_t a_r = lane & 15, a_c = (lane >> 4) * 16;
    const uint32_t b_r = (lane & 7) + ((lane >> 4) & 1) * 8;
    const uint32_t b_c = ((lane >> 3) & 1) * 16;
    const int lrow = tid >> 1, lhalf = tid & 1;
    const uint32_t so = (uint32_t)lrow * TSTRB + lhalf * 64;

    for (int kc = 0; kc < EMBED; kc += 64) {
        __syncthreads();
        {
            size_t ao = (size_t)(row0 + lrow) * EMBED + kc + lhalf * 32;
            size_t bo = (size_t)(col0 + lrow) * EMBED + kc + lhalf * 32;
            const uint4* ahp = (const uint4*)(ah + ao);
            const uint4* alp = (const uint4*)(al + ao);
            const uint4* bhp = (const uint4*)(wth + bo);
            const uint4* blp = (const uint4*)(wtl + bo);
            #pragma unroll
            for (int i = 0; i < 4; i++) {
                *(uint4*)(smem + OA_H + so + i * 16) = ahp[i];
                *(uint4*)(smem + OA_L + so + i * 16) = alp[i];
                *(uint4*)(smem + OB_H + so + i * 16) = bhp[i];
                *(uint4*)(smem + OB_L + so + i * 16) = blp[i];
            }
        }
        __syncthreads();

        #pragma unroll
        for (int ks = 0; ks < 4; ks++) {
            const uint32_t kb = ks * 32;
            uint32_t a[4][4], bhf[2][4], blf[2][4];
            #pragma unroll
            for (int mf = 0; mf < 4; mf++) {
                uint32_t ad = sb + OA_H + (wm * 64 + mf * 16 + a_r) * TSTRB + kb + a_c;
                LDSM_X4(a[mf][0], a[mf][1], a[mf][2], a[mf][3], ad);
            }
            #pragma unroll
            for (int p = 0; p < 2; p++) {
                uint32_t bd = sb + OB_H + (wn * 32 + p * 16 + b_r) * TSTRB + kb + b_c;
                LDSM_X4(bhf[p][0], bhf[p][1], bhf[p][2], bhf[p][3], bd);
            }
            #pragma unroll
            for (int p = 0; p < 2; p++) {
                uint32_t bd = sb + OB_L + (wn * 32 + p * 16 + b_r) * TSTRB + kb + b_c;
                LDSM_X4(blf[p][0], blf[p][1], blf[p][2], blf[p][3], bd);
            }
            #pragma unroll
            for (int mf = 0; mf < 4; mf++)
                #pragma unroll
                for (int nf = 0; nf < 4; nf++) {
                    MMA_BF16(acc[mf][nf], a[mf][0], a[mf][1], a[mf][2], a[mf][3],
                             bhf[nf >> 1][(nf & 1) * 2], bhf[nf >> 1][(nf & 1) * 2 + 1]);
                    MMA_BF16(acc[mf][nf], a[mf][0], a[mf][1], a[mf][2], a[mf][3],
                             blf[nf >> 1][(nf & 1) * 2], blf[nf >> 1][(nf & 1) * 2 + 1]);
                }
            #pragma unroll
            for (int mf = 0; mf < 4; mf++) {
                uint32_t ad = sb + OA_L + (wm * 64 + mf * 16 + a_r) * TSTRB + kb + a_c;
                LDSM_X4(a[mf][0], a[mf][1], a[mf][2], a[mf][3], ad);
            }
            #pragma unroll
            for (int mf = 0; mf < 4; mf++)
                #pragma unroll
                for (int nf = 0; nf < 4; nf++)
                    MMA_BF16(acc[mf][nf], a[mf][0], a[mf][1], a[mf][2], a[mf][3],
                             bhf[nf >> 1][(nf & 1) * 2], bhf[nf >> 1][(nf & 1) * 2 + 1]);
        }
    }

    const int er = lane >> 2, ec = (lane & 3) * 2;
    #pragma unroll
    for (int mf = 0; mf < 4; mf++) {
        int r = row0 + wm * 64 + mf * 16 + er;
        #pragma unroll
        for (int nf = 0; nf < 4; nf++) {
            int c = col0 + wn * 32 + nf * 8 + ec;
            float b0 = bias[c], b1 = bias[c + 1];
            float v00 = acc[mf][nf][0] + b0, v01 = acc[mf][nf][1] + b1;
            float v10 = acc[mf][nf][2] + b0, v11 = acc[mf][nf][3] + b1;
            if (mode == 0) {
                *(float2*)&cf[(size_t)r * EMBED + c] = make_float2(v00, v01);
                *(float2*)&cf[(size_t)(r + 8) * EMBED + c] = make_float2(v10, v11);
            } else {
                uint32_t h0, l0, h1, l1;
                split2(v00, v01, h0, l0);
                split2(v10, v11, h1, l1);
                *(uint32_t*)&ch[(size_t)r * EMBED + c] = h0;
                *(uint32_t*)&cl[(size_t)r * EMBED + c] = l0;
                *(uint32_t*)&ch[(size_t)(r + 8) * EMBED + c] = h1;
                *(uint32_t*)&cl[(size_t)(r + 8) * EMBED + c] = l1;
            }
        }
    }
}

// ---------------------------------------------------------------------------
// Scores via mma.sync [R4 verbatim]
// ---------------------------------------------------------------------------
#define SC_SMEM (4 * TILE128B) /* 73728 */
__global__ __launch_bounds__(256) void scores_mma(
    const __nv_bfloat16* __restrict__ qh, const __nv_bfloat16* __restrict__ ql,
    const __nv_bfloat16* __restrict__ kh, const __nv_bfloat16* __restrict__ kl,
    float* __restrict__ attn)
{
    extern __shared__ char smem[];
    const uint32_t sb = smem_u32(smem);
    const int tid = threadIdx.x, wid = tid >> 5, lane = tid & 31;
    const int bh = blockIdx.z, b = bh >> 3, h = bh & 7;
    const int row0 = blockIdx.y * 128, col0 = blockIdx.x * 128;
    const uint32_t OA_H = 0, OA_L = TILE128B, OB_H = 2 * TILE128B, OB_L = 3 * TILE128B;

    {
        const int lrow = tid >> 1, lhalf = tid & 1;
        size_t qo = (size_t)(b * SS + row0 + lrow) * EMBED + h * HD + lhalf * 32;
        size_t ko = (size_t)(b * SS + col0 + lrow) * EMBED + h * HD + lhalf * 32;
        const uint4* qhp = (const uint4*)(qh + qo);
        const uint4* qlp = (const uint4*)(ql + qo);
        const uint4* khp = (const uint4*)(kh + ko);
        const uint4* klp = (const uint4*)(kl + ko);
        const uint32_t so = (uint32_t)lrow * TSTRB + lhalf * 64;
        #pragma unroll
        for (int i = 0; i < 4; i++) {
            *(uint4*)(smem + OA_H + so + i * 16) = qhp[i];
            *(uint4*)(smem + OA_L + so + i * 16) = qlp[i];
            *(uint4*)(smem + OB_H + so + i * 16) = khp[i];
            *(uint4*)(smem + OB_L + so + i * 16) = klp[i];
        }
    }
    __syncthreads();

    const int wm = wid >> 2, wn = wid & 3;
    float acc[4][4][4] = {};
    const uint32_t a_r = lane & 15, a_c = (lane >> 4) * 16;
    const uint32_t b_r = (lane & 7) + ((lane >> 4) & 1) * 8;
    const uint32_t b_c = ((lane >> 3) & 1) * 16;

    #pragma unroll
    for (int ks = 0; ks < 4; ks++) {
        const uint32_t kb = ks * 32;
        uint32_t a[4][4], bhf[2][4], blf[2][4];
        #pragma unroll
        for (int mf = 0; mf < 4; mf++) {
            uint32_t ad = sb + OA_H + (wm * 64 + mf * 16 + a_r) * TSTRB + kb + a_c;
            LDSM_X4(a[mf][0], a[mf][1], a[mf][2], a[mf][3], ad);
        }
        #pragma unroll
        for (int p = 0; p < 2; p++) {
            uint32_t bd = sb + OB_H + (wn * 32 + p * 16 + b_r) * TSTRB + kb + b_c;
            LDSM_X4(bhf[p][0], bhf[p][1], bhf[p][2], bhf[p][3], bd);
        }
        #pragma unroll
        for (int p = 0; p < 2; p++) {
            uint32_t bd = sb + OB_L + (wn * 32 + p * 16 + b_r) * TSTRB + kb + b_c;
            LDSM_X4(blf[p][0], blf[p][1], blf[p][2], blf[p][3], bd);
        }
        #pragma unroll
        for (int mf = 0; mf < 4; mf++)
            #pragma unroll
            for (int nf = 0; nf < 4; nf++) {
                MMA_BF16(acc[mf][nf], a[mf][0], a[mf][1], a[mf][2], a[mf][3],
                         bhf[nf >> 1][(nf & 1) * 2], bhf[nf >> 1][(nf & 1) * 2 + 1]);
                MMA_BF16(acc[mf][nf], a[mf][0], a[mf][1], a[mf][2], a[mf][3],
                         blf[nf >> 1][(nf & 1) * 2], blf[nf >> 1][(nf & 1) * 2 + 1]);
            }
        #pragma unroll
        for (int mf = 0; mf < 4; mf++) {
            uint32_t ad = sb + OA_L + (wm * 64 + mf * 16 + a_r) * TSTRB + kb + a_c;
            LDSM_X4(a[mf][0], a[mf][1], a[mf][2], a[mf][3], ad);
        }
        #pragma unroll
        for (int mf = 0; mf < 4; mf++)
            #pragma unroll
            for (int nf = 0; nf < 4; nf++)
                MMA_BF16(acc[mf][nf], a[mf][0], a[mf][1], a[mf][2], a[mf][3],
                         bhf[nf >> 1][(nf & 1) * 2], bhf[nf >> 1][(nf & 1) * 2 + 1]);
    }

    float* outp = attn + (size_t)bh * SS * SS;
    const int er = lane >> 2, ec = (lane & 3) * 2;
    #pragma unroll
    for (int mf = 0; mf < 4; mf++) {
        int r = row0 + wm * 64 + mf * 16 + er;
        #pragma unroll
        for (int nf = 0; nf < 4; nf++) {
            int c = col0 + wn * 32 + nf * 8 + ec;
            *(float2*)&outp[(size_t)r * SS + c] =
                make_float2(acc[mf][nf][0] * 0.125f, acc[mf][nf][1] * 0.125f);
            *(float2*)&outp[(size_t)(r + 8) * SS + c] =
                make_float2(acc[mf][nf][2] * 0.125f, acc[mf][nf][3] * 0.125f);
        }
    }
}

// ---------------------------------------------------------------------------
// Row softmax in place (rows of 2048), float4 I/O
// ---------------------------------------------------------------------------
__global__ __launch_bounds__(256) void softmax_kernel(float* __restrict__ attn)
{
    float4* p = (float4*)(attn + (size_t)blockIdx.x * SS);
    const int tid = threadIdx.x;
    const int w = tid >> 5, l = tid & 31;
    __shared__ float smax[8];
    __shared__ float ssum[8];
    float4 v0 = p[tid], v1 = p[tid + 256];

    float m = fmaxf(fmaxf(fmaxf(v0.x, v0.y), fmaxf(v0.z, v0.w)),
                    fmaxf(fmaxf(v1.x, v1.y), fmaxf(v1.z, v1.w)));
    #pragma unroll
    for (int o = 16; o > 0; o >>= 1) m = fmaxf(m, __shfl_xor_sync(0xffffffffu, m, o));
    if (l == 0) smax[w] = m;
    __syncthreads();
    float bm = smax[0];
    #pragma unroll
    for (int i = 1; i < 8; i++) bm = fmaxf(bm, smax[i]);

    v0.x = __expf(v0.x - bm); v0.y = __expf(v0.y - bm);
    v0.z = __expf(v0.z - bm); v0.w = __expf(v0.w - bm);
    v1.x = __expf(v1.x - bm); v1.y = __expf(v1.y - bm);
    v1.z = __expf(v1.z - bm); v1.w = __expf(v1.w - bm);
    float s = (v0.x + v0.y) + (v0.z + v0.w) + (v1.x + v1.y) + (v1.z + v1.w);
    #pragma unroll
    for (int o = 16; o > 0; o >>= 1) s += __shfl_xor_sync(0xffffffffu, s, o);
    if (l == 0) ssum[w] = s;
    __syncthreads();
    float bs = 0.f;
    #pragma unroll
    for (int i = 0; i < 8; i++) bs += ssum[i];

    const float inv = 1.0f / bs;
    v0.x *= inv; v0.y *= inv; v0.z *= inv; v0.w *= inv;
    v1.x *= inv; v1.y *= inv; v1.z *= inv; v1.w *= inv;
    p[tid] = v0;
    p[tid + 256] = v1;
}

// ---------------------------------------------------------------------------
// Context via mma.sync [R4 verbatim]: ctx -> bf16 hi/lo
// ---------------------------------------------------------------------------
#define CTX_SMEM (2 * TILE128B + 2 * TILE64B) /* 55296 */
__global__ __launch_bounds__(256) void context_mma(
    const float* __restrict__ attn,
    const __nv_bfloat16* __restrict__ vth, const __nv_bfloat16* __restrict__ vtl,
    __nv_bfloat16* __restrict__ ctxh, __nv_bfloat16* __restrict__ ctxl)
{
    extern __shared__ char smem[];
    const uint32_t sb = smem_u32(smem);
    const int tid = threadIdx.x, wid = tid >> 5, lane = tid & 31;
    const int bh = blockIdx.y, b = bh >> 3, h = bh & 7;
    const int row0 = blockIdx.x * 128;
    const uint32_t OA_H = 0, OA_L = TILE128B, OB_H = 2 * TILE128B, OB_L = 2 * TILE128B + TILE64B;

    const float* ap = attn + (size_t)bh * SS * SS;
    const __nv_bfloat16* bhp = vth + (size_t)bh * HD * SS;
    const __nv_bfloat16* blp = vtl + (size_t)bh * HD * SS;

    const int wm = wid >> 1, wn = wid & 1;
    float acc[2][4][4] = {};

    const uint32_t a_r = lane & 15, a_c = (lane >> 4) * 16;
    const uint32_t b_r = (lane & 7) + ((lane >> 4) & 1) * 8;
    const uint32_t b_c = ((lane >> 3) & 1) * 16;

    const int arow = tid >> 1, ahalf = tid & 1;
    const int brow = tid >> 2, bq = tid & 3;

    for (int t = 0; t < 32; t++) {
        __syncthreads();
        {
            const float4* src = (const float4*)(ap + (size_t)(row0 + arow) * SS + t * 64 + ahalf * 32);
            const uint32_t so = (uint32_t)arow * TSTRB + ahalf * 64;
            #pragma unroll
            for (int i = 0; i < 8; i++) {
                float4 f = src[i];
                uint32_t h0, l0, h1, l1;
                split2(f.x, f.y, h0, l0);
                split2(f.z, f.w, h1, l1);
                *(uint2*)(smem + OA_H + so + i * 8) = make_uint2(h0, h1);
                *(uint2*)(smem + OA_L + so + i * 8) = make_uint2(l0, l1);
            }
        }
        {
            size_t o = (size_t)brow * SS + t * 64 + bq * 16;
            const uint4* sh = (const uint4*)(bhp + o);
            const uint4* sl = (const uint4*)(blp + o);
            const uint32_t so = (uint32_t)brow * TSTRB + bq * 32;
            #pragma unroll
            for (int i = 0; i < 2; i++) {
                *(uint4*)(smem + OB_H + so + i * 16) = sh[i];
                *(uint4*)(smem + OB_L + so + i * 16) = sl[i];
            }
        }
        __syncthreads();

        #pragma unroll
        for (int ks = 0; ks < 4; ks++) {
            const uint32_t kb = ks * 32;
            uint32_t a[2][4], bhf[2][4], blf[2][4];
            #pragma unroll
            for (int mf = 0; mf < 2; mf++) {
                uint32_t ad = sb + OA_H + (wm * 32 + mf * 16 + a_r) * TSTRB + kb + a_c;
                LDSM_X4(a[mf][0], a[mf][1], a[mf][2], a[mf][3], ad);
            }
            #pragma unroll
            for (int p = 0; p < 2; p++) {
                uint32_t bd = sb + OB_H + (wn * 32 + p * 16 + b_r) * TSTRB + kb + b_c;
                LDSM_X4(bhf[p][0], bhf[p][1], bhf[p][2], bhf[p][3], bd);
            }
            #pragma unroll
            for (int p = 0; p < 2; p++) {
                uint32_t bd = sb + OB_L + (wn * 32 + p * 16 + b_r) * TSTRB + kb + b_c;
                LDSM_X4(blf[p][0], blf[p][1], blf[p][2], blf[p][3], bd);
            }
            #pragma unroll
            for (int mf = 0; mf < 2; mf++)
                #pragma unroll
                for (int nf = 0; nf < 4; nf++) {
                    MMA_BF16(acc[mf][nf], a[mf][0], a[mf][1], a[mf][2], a[mf][3],
                             bhf[nf >> 1][(nf & 1) * 2], bhf[nf >> 1][(nf & 1) * 2 + 1]);
                    MMA_BF16(acc[mf][nf], a[mf][0], a[mf][1], a[mf][2], a[mf][3],
                             blf[nf >> 1][(nf & 1) * 2], blf[nf >> 1][(nf & 1) * 2 + 1]);
                }
            #pragma unroll
            for (int mf = 0; mf < 2; mf++) {
                uint32_t ad = sb + OA_L + (wm * 32 + mf * 16 + a_r) * TSTRB + kb + a_c;
                LDSM_X4(a[mf][0], a[mf][1], a[mf][2], a[mf][3], ad);
            }
            #pragma unroll
            for (int mf = 0; mf < 2; mf++)
                #pragma unroll
                for (int nf = 0; nf < 4; nf++)
                    MMA_BF16(acc[mf][nf], a[mf][0], a[mf][1], a[mf][2], a[mf][3],
                             bhf[nf >> 1][(nf & 1) * 2], bhf[nf >> 1][(nf & 1) * 2 + 1]);
        }
    }

    const int er = lane >> 2, ec = (lane & 3) * 2;
    #pragma unroll
    for (int mf = 0; mf < 2; mf++) {
        int r = row0 + wm * 32 + mf * 16 + er;
        #pragma unroll
        for (int nf = 0; nf < 4; nf++) {
            int c = wn * 32 + nf * 8 + ec;
            uint32_t h0, l0, h1, l1;
            split2(acc[mf][nf][0], acc[mf][nf][1], h0, l0);
            split2(acc[mf][nf][2], acc[mf][nf][3], h1, l1);
            size_t o0 = (size_t)(b * SS + r) * EMBED + h * HD + c;
            size_t o1 = (size_t)(b * SS + r + 8) * EMBED + h * HD + c;
            *(uint32_t*)&ctxh[o0] = h0;
            *(uint32_t*)&ctxl[o0] = l0;
            *(uint32_t*)&ctxh[o1] = h1;
            *(uint32_t*)&ctxl[o1] = l1;
        }
    }
}

// ---------------------------------------------------------------------------
extern "C" void kernel_launch(void* const* d_in, const int* in_sizes, int n_in,
                              void* d_out, int out_size)
{
    const float* query = (const float*)d_in[0];
    const float* key   = (const float*)d_in[1];
    const float* value = (const float*)d_in[2];
    const float* Wq = (const float*)d_in[3];
    const float* bq = (const float*)d_in[4];
    const float* Wk = (const float*)d_in[5];
    const float* bk = (const float*)d_in[6];
    const float* Wv = (const float*)d_in[7];
    const float* bv = (const float*)d_in[8];
    const float* Wo = (const float*)d_in[9];
    const float* bo = (const float*)d_in[10];
    float* out = (float*)d_out;

    const size_t out_elems  = (size_t)MROWS * EMBED;
    const size_t attn_elems = (size_t)NBH * SS * SS;
    const size_t wsz = (size_t)EMBED * EMBED;

    float *pv, *pattn;
    __nv_bfloat16 *pt1h, *pt1l, *pt2h, *pt2l, *pt3h, *pt3l;
    __nv_bfloat16 *pqh, *pql, *pkh, *pkl, *pctxh, *pctxl, *pvth, *pvtl, *pwth, *pwtl;
    cudaGetSymbolAddress((void**)&pv,    g_v);
    cudaGetSymbolAddress((void**)&pattn, g_attn);
    cudaGetSymbolAddress((void**)&pt1h,  g_t1h);
    cudaGetSymbolAddress((void**)&pt1l,  g_t1l);
    cudaGetSymbolAddress((void**)&pt2h,  g_t2h);
    cudaGetSymbolAddress((void**)&pt2l,  g_t2l);
    cudaGetSymbolAddress((void**)&pt3h,  g_t3h);
    cudaGetSymbolAddress((void**)&pt3l,  g_t3l);
    cudaGetSymbolAddress((void**)&pqh,   g_qh);
    cudaGetSymbolAddress((void**)&pql,   g_ql);
    cudaGetSymbolAddress((void**)&pkh,   g_kh);
    cudaGetSymbolAddress((void**)&pkl,   g_kl);
    cudaGetSymbolAddress((void**)&pctxh, g_ctxh);
    cudaGetSymbolAddress((void**)&pctxl, g_ctxl);
    cudaGetSymbolAddress((void**)&pvth,  g_vth);
    cudaGetSymbolAddress((void**)&pvtl,  g_vtl);
    cudaGetSymbolAddress((void**)&pwth,  g_wth);
    cudaGetSymbolAddress((void**)&pwtl,  g_wtl);

    float* attn = ((size_t)out_size >= out_elems + attn_elems) ? (out + out_elems) : pattn;

    cudaFuncSetAttribute(proj_mma, cudaFuncAttributeMaxDynamicSharedMemorySize, PRJ_SMEM);
    cudaFuncSetAttribute(scores_mma, cudaFuncAttributeMaxDynamicSharedMemorySize, SC_SMEM);
    cudaFuncSetAttribute(context_mma, cudaFuncAttributeMaxDynamicSharedMemorySize, CTX_SMEM);

    // weight transpose + split (1 launch)
    split_wT_all<<<dim3(EMBED / 32, EMBED / 32, 4), dim3(32, 8)>>>(Wq, Wk, Wv, Wo, pwth, pwtl);

    // input hi/lo splits (1 launch, all 3 inputs)
    const int n4 = (MROWS * EMBED) / 4;
    split_hl_all<<<dim3(n4 / 256, 3), 256>>>(
        (const float4*)query, (const float4*)key, (const float4*)value,
        (uint2*)pt1h, (uint2*)pt1l, (uint2*)pt2h, (uint2*)pt2l, (uint2*)pt3h, (uint2*)pt3l, n4);

    dim3 gP(EMBED / 128, MROWS / 128);
    proj_mma<<<gP, 256, PRJ_SMEM>>>(pt1h, pt1l, pwth + 0 * wsz, pwtl + 0 * wsz, bq,
                                    nullptr, pqh, pql, 1);
    proj_mma<<<gP, 256, PRJ_SMEM>>>(pt2h, pt2l, pwth + 1 * wsz, pwtl + 1 * wsz, bk,
                                    nullptr, pkh, pkl, 1);
    proj_mma<<<gP, 256, PRJ_SMEM>>>(pt3h, pt3l, pwth + 2 * wsz, pwtl + 2 * wsz, bv,
                                    pv, nullptr, nullptr, 0);
    split_vT_kernel<<<dim3(SS / 32, HD / 32, NBH), dim3(32, 8)>>>(pv, pvth, pvtl);

    scores_mma<<<dim3(SS / 128, SS / 128, NBH), 256, SC_SMEM>>>(pqh, pql, pkh, pkl, attn);

    softmax_kernel<<<NBH * SS, 256>>>(attn);

    context_mma<<<dim3(SS / 128, NBH), 256, CTX_SMEM>>>(attn, pvth, pvtl, pctxh, pctxl);

    proj_mma<<<gP, 256, PRJ_SMEM>>>(pctxh, pctxl, pwth + 3 * wsz, pwtl + 3 * wsz, bo,
                                    out, nullptr, nullptr, 0);
}